// round 4
// baseline (speedup 1.0000x reference)
#include <cuda_runtime.h>
#include <cuda_bf16.h>
#include <math.h>
#include <stdint.h>

#define K_DIM 1024
#define N_DIM 16384

// ---------------------------------------------------------------------------
// Scratch (static device globals — no dynamic allocation allowed)
// ---------------------------------------------------------------------------
__device__ __nv_bfloat16 g_Gb[(size_t)N_DIM * K_DIM];   // G[t][k] bf16, 32 MB
__device__ __nv_bfloat16 g_Ab[(size_t)K_DIM * K_DIM];   // Alpha bf16, 2 MB
__device__ float  g_rowsum[K_DIM];
__device__ float  g_Mu0[K_DIM];
__device__ double g_loglik;

// ---------------------------------------------------------------------------
// PTX helpers (baseline sm_80+ features only — tcgen05 not available via this
// toolchain: harness compiles for plain sm_103, arch-accelerated ops rejected)
// ---------------------------------------------------------------------------
__device__ __forceinline__ uint32_t smem_u32(const void* p) {
    uint32_t a;
    asm("{ .reg .u64 t; cvta.to.shared.u64 t, %1; cvt.u32.u64 %0, t; }"
        : "=r"(a) : "l"(p));
    return a;
}
__device__ __forceinline__ void cp16(uint32_t dst, const void* src) {
    asm volatile("cp.async.cg.shared.global [%0], [%1], 16;"
                 :: "r"(dst), "l"(src) : "memory");
}
#define CP_COMMIT() asm volatile("cp.async.commit_group;" ::: "memory")
#define CP_WAIT(n)  asm volatile("cp.async.wait_group %0;" :: "n"(n) : "memory")

__device__ __forceinline__ void ldsm4(uint32_t* r, uint32_t addr) {
    asm volatile("ldmatrix.sync.aligned.m8n8.x4.shared.b16 {%0,%1,%2,%3}, [%4];"
                 : "=r"(r[0]), "=r"(r[1]), "=r"(r[2]), "=r"(r[3]) : "r"(addr));
}
__device__ __forceinline__ void mma16816(float* c, const uint32_t* a,
                                         uint32_t b0, uint32_t b1) {
    asm volatile(
        "mma.sync.aligned.m16n8k16.row.col.f32.bf16.bf16.f32 "
        "{%0,%1,%2,%3}, {%4,%5,%6,%7}, {%8,%9}, {%0,%1,%2,%3};"
        : "+f"(c[0]), "+f"(c[1]), "+f"(c[2]), "+f"(c[3])
        : "r"(a[0]), "r"(a[1]), "r"(a[2]), "r"(a[3]), "r"(b0), "r"(b1));
}

// ---------------------------------------------------------------------------
// Alpha fp32 -> bf16; block 0 also zeroes the accumulators (fresh every replay)
// ---------------------------------------------------------------------------
__global__ void conv_alpha_kernel(const float* __restrict__ A) {
    if (blockIdx.x == 0) {
        #pragma unroll
        for (int r = 0; r < 4; ++r) g_rowsum[threadIdx.x * 4 + r] = 0.f;
        if (threadIdx.x == 0) g_loglik = 0.0;
    }
    size_t i = ((size_t)blockIdx.x * blockDim.x + threadIdx.x) * 4;
    float4 v = *reinterpret_cast<const float4*>(A + i);
    *reinterpret_cast<__nv_bfloat162*>(&g_Ab[i])     = __floats2bfloat162_rn(v.x, v.y);
    *reinterpret_cast<__nv_bfloat162*>(&g_Ab[i + 2]) = __floats2bfloat162_rn(v.z, v.w);
}

// ---------------------------------------------------------------------------
// Fused transpose + exponential scan with 64-step halo (decay <= e^-1 =>
// halo truncation error ~ e^-64, invisible) + row-sum accumulation for Mu0.
// ---------------------------------------------------------------------------
__global__ __launch_bounds__(256)
void scan_kernel(const float* __restrict__ obs, const float* __restrict__ Beta) {
    __shared__ float tile[32][321];
    const int k0 = blockIdx.y * 32;
    const int t0 = blockIdx.x * 256;
    const int tid = threadIdx.x;
    const int lane = tid & 31;
    const int tstart = t0 - 64;

    int rbase = (tid >> 5) * 4;
    float rs[4];
    #pragma unroll
    for (int r = 0; r < 4; ++r) {
        const float* src = obs + (size_t)(k0 + rbase + r) * N_DIM;
        float acc = 0.f;
        #pragma unroll
        for (int i = 0; i < 10; ++i) {
            int col = lane + i * 32;
            int t = tstart + col;
            float v = (t >= 0) ? src[t] : 0.f;
            tile[rbase + r][col] = v;
            if (i >= 2) acc += v;          // emit region only (cols 64..319)
        }
        rs[r] = acc;
    }
    // warp-reduce the 4 row partials, accumulate into g_rowsum
    #pragma unroll
    for (int r = 0; r < 4; ++r) {
        float v = rs[r];
        #pragma unroll
        for (int off = 16; off > 0; off >>= 1)
            v += __shfl_down_sync(0xFFFFFFFFu, v, off);
        if (lane == 0) atomicAdd(&g_rowsum[k0 + rbase + r], v);
    }
    __syncthreads();

    if (tid < 32) {
        float beta = Beta[k0 + tid];
        float dec = __expf(-beta);
        float S = 0.f;
        #pragma unroll 8
        for (int i = 0; i < 64; ++i) S = dec * (S + tile[tid][i]);
        #pragma unroll 4
        for (int i = 0; i < 256; ++i) {
            g_Gb[(size_t)(t0 + i) * K_DIM + k0 + tid] = __float2bfloat16(beta * S);
            S = dec * (S + tile[tid][64 + i]);
        }
    }
}

// Mu0 finalize (after all scan atomics)
__global__ void mu_kernel() {
    int k = threadIdx.x;
    g_Mu0[k] = g_rowsum[k] * (1.0f / (float)N_DIM) * 0.1f + 1e-5f;
}

// ---------------------------------------------------------------------------
// bf16 tensor-core GEMM (mma.sync m16n8k16) + fused epilogue.
// C[t][ko] = sum_j G[t][j]*Alpha[ko][j]; lam1=softplus(C); lam1[:,0]=0;
// loglik += sum(obs*log(mu+lam1+1e-5) - mu - lam1); write lam1 and lams0.
//
// CTA tile 128(t) x 256(ko), BK=32, 4-stage cp.async pipeline, 8 warps:
// wm = wid&1 (2 m-warps of 64), wn = wid>>1 (4 n-warps of 64 -> 64x64/warp).
// SMEM rows padded to 40 bf16 (80B): row stride 20 words -> each ldmatrix
// 8-row phase hits distinct banks (20r mod 32 distinct for r=0..7).
// ---------------------------------------------------------------------------
#define STAGES 4
#define A_TILE_B (128 * 80)            // 10240
#define B_TILE_B (256 * 80)            // 20480
#define STAGE_B  (A_TILE_B + B_TILE_B) // 30720
#define GEMM_SMEM (STAGES * STAGE_B)   // 122880

__global__ __launch_bounds__(256, 1)
void gemm_ep_kernel(const float* __restrict__ obs,
                    float* __restrict__ out_lams0,
                    float* __restrict__ out_lam1, int do_write) {
    extern __shared__ char smem[];
    const uint32_t sb = smem_u32(smem);
    const int tid = threadIdx.x;
    const int wid = tid >> 5;
    const int lane = tid & 31;
    const int wm = wid & 1;
    const int wn = wid >> 1;
    const int ko0 = blockIdx.x * 256;
    const int t0  = blockIdx.y * 128;

    const int lrow = tid >> 2;        // 0..63
    const int lch  = tid & 3;         // 0..3

    auto load_stage = [&](int s, int j0) {
        if (j0 < K_DIM) {
            uint32_t abase = sb + s * STAGE_B;
            uint32_t bbase = abase + A_TILE_B;
            #pragma unroll
            for (int p = 0; p < 2; ++p) {
                int row = lrow + p * 64;
                cp16(abase + row * 80 + lch * 16,
                     g_Gb + (size_t)(t0 + row) * K_DIM + j0 + lch * 8);
            }
            #pragma unroll
            for (int p = 0; p < 4; ++p) {
                int row = lrow + p * 64;
                cp16(bbase + row * 80 + lch * 16,
                     g_Ab + (size_t)(ko0 + row) * K_DIM + j0 + lch * 8);
            }
        }
        CP_COMMIT();
    };

    load_stage(0, 0);
    load_stage(1, 32);
    load_stage(2, 64);

    float acc[4][8][4];
    #pragma unroll
    for (int i = 0; i < 4; ++i)
        #pragma unroll
        for (int j = 0; j < 8; ++j)
            #pragma unroll
            for (int e = 0; e < 4; ++e) acc[i][j][e] = 0.f;

    const uint32_t lr = (lane & 15);
    const uint32_t lh = (lane >> 4) * 16;

    #pragma unroll 1
    for (int it = 0; it < 32; ++it) {
        CP_WAIT(2);
        __syncthreads();
        load_stage((it + 3) & 3, (it + 3) * 32);

        uint32_t abase = sb + (it & 3) * STAGE_B;
        uint32_t bbase = abase + A_TILE_B;
        #pragma unroll
        for (int kk = 0; kk < 2; ++kk) {
            uint32_t a[4][4], b[4][4];
            #pragma unroll
            for (int mi = 0; mi < 4; ++mi)
                ldsm4(a[mi], abase + (wm * 64 + mi * 16 + lr) * 80 + lh + kk * 32);
            #pragma unroll
            for (int ng = 0; ng < 4; ++ng)
                ldsm4(b[ng], bbase + (wn * 64 + ng * 16 + lr) * 80 + lh + kk * 32);
            #pragma unroll
            for (int mi = 0; mi < 4; ++mi)
                #pragma unroll
                for (int ni = 0; ni < 8; ++ni)
                    mma16816(acc[mi][ni], a[mi],
                             b[ni >> 1][ni & 1], b[ni >> 1][2 + (ni & 1)]);
        }
    }

    // ---- fused epilogue straight from mma fragments ----
    float lsum = 0.f;
    #pragma unroll
    for (int mi = 0; mi < 4; ++mi) {
        #pragma unroll
        for (int ni = 0; ni < 8; ++ni) {
            const int tb = t0 + wm * 64 + mi * 16 + (lane >> 2);
            const int kb = ko0 + wn * 64 + ni * 8 + (lane & 3) * 2;
            #pragma unroll
            for (int e = 0; e < 4; ++e) {
                const int t  = tb + (e >> 1) * 8;
                const int ko = kb + (e & 1);
                float x = acc[mi][ni][e];
                float lam1 = (x > 20.f) ? x : __logf(1.f + __expf(x));
                if (t == 0) lam1 = 0.f;
                float mu = g_Mu0[ko];
                float o = __ldg(obs + (size_t)ko * N_DIM + t);
                lsum += o * __logf(mu + lam1 + 1e-5f) - mu - lam1;
                if (do_write) {
                    out_lam1[(size_t)ko * N_DIM + t]  = lam1;
                    out_lams0[(size_t)ko * N_DIM + t] = mu;
                }
            }
        }
    }

    __syncthreads();
    float* red = reinterpret_cast<float*>(smem);
    red[tid] = lsum;
    __syncthreads();
    for (int off = 128; off > 0; off >>= 1) {
        if (tid < off) red[tid] += red[tid + off];
        __syncthreads();
    }
    if (tid == 0) atomicAdd(&g_loglik, (double)red[0]);
}

__global__ void finalize_kernel(float* __restrict__ out) {
    out[0] = (float)g_loglik;
}

// ---------------------------------------------------------------------------
extern "C" void kernel_launch(void* const* d_in, const int* in_sizes, int n_in,
                              void* d_out, int out_size) {
    const float *obs = nullptr, *Beta = nullptr, *Alpha = nullptr;
    for (int i = 0; i < n_in; ++i) {
        if (in_sizes[i] == K_DIM) Beta = (const float*)d_in[i];
        else if (in_sizes[i] == K_DIM * K_DIM) Alpha = (const float*)d_in[i];
        else if ((size_t)in_sizes[i] == (size_t)K_DIM * N_DIM) obs = (const float*)d_in[i];
    }
    float* out = (float*)d_out;
    const long long full_sz = 1LL + 2LL * K_DIM * N_DIM;
    int full = ((long long)out_size >= full_sz) ? 1 : 0;
    float* out_lams0 = out + 1;
    float* out_lam1  = out + 1 + (size_t)K_DIM * N_DIM;

    static int smem_set = 0;
    if (!smem_set) {
        cudaFuncSetAttribute(gemm_ep_kernel,
                             cudaFuncAttributeMaxDynamicSharedMemorySize, GEMM_SMEM);
        smem_set = 1;
    }

    conv_alpha_kernel<<<(K_DIM * K_DIM) / (256 * 4), 256>>>(Alpha);
    dim3 sgrid(N_DIM / 256, K_DIM / 32);
    scan_kernel<<<sgrid, 256>>>(obs, Beta);
    mu_kernel<<<1, K_DIM>>>();
    dim3 ggrid(K_DIM / 256, N_DIM / 128);
    gemm_ep_kernel<<<ggrid, 256, GEMM_SMEM>>>(obs, out_lams0, out_lam1, full);
    finalize_kernel<<<1, 1>>>(out);
}

// round 5
// speedup vs baseline: 1.0410x; 1.0410x over previous
#include <cuda_runtime.h>
#include <cuda_bf16.h>
#include <math.h>
#include <stdint.h>

#define K_DIM 1024
#define N_DIM 16384

// ---------------------------------------------------------------------------
// Scratch (static device globals — no dynamic allocation allowed)
// ---------------------------------------------------------------------------
__device__ __nv_bfloat16 g_Gb[(size_t)N_DIM * K_DIM];   // G[t][k] bf16, 32 MB
__device__ __nv_bfloat16 g_Ab[(size_t)K_DIM * K_DIM];   // Alpha bf16, 2 MB
__device__ float  g_rowsum[K_DIM];
__device__ float  g_Mu0[K_DIM];
__device__ double g_loglik;

// ---------------------------------------------------------------------------
// PTX helpers (baseline sm_80+ features only — tcgen05 not available via this
// toolchain: harness compiles for plain sm_103, arch-accelerated ops rejected)
// ---------------------------------------------------------------------------
__device__ __forceinline__ uint32_t smem_u32(const void* p) {
    uint32_t a;
    asm("{ .reg .u64 t; cvta.to.shared.u64 t, %1; cvt.u32.u64 %0, t; }"
        : "=r"(a) : "l"(p));
    return a;
}
__device__ __forceinline__ void cp16(uint32_t dst, const void* src) {
    asm volatile("cp.async.cg.shared.global [%0], [%1], 16;"
                 :: "r"(dst), "l"(src) : "memory");
}
#define CP_COMMIT() asm volatile("cp.async.commit_group;" ::: "memory")
#define CP_WAIT(n)  asm volatile("cp.async.wait_group %0;" :: "n"(n) : "memory")

__device__ __forceinline__ void ldsm4(uint32_t* r, uint32_t addr) {
    asm volatile("ldmatrix.sync.aligned.m8n8.x4.shared.b16 {%0,%1,%2,%3}, [%4];"
                 : "=r"(r[0]), "=r"(r[1]), "=r"(r[2]), "=r"(r[3]) : "r"(addr));
}
__device__ __forceinline__ void mma16816(float* c, const uint32_t* a,
                                         uint32_t b0, uint32_t b1) {
    asm volatile(
        "mma.sync.aligned.m16n8k16.row.col.f32.bf16.bf16.f32 "
        "{%0,%1,%2,%3}, {%4,%5,%6,%7}, {%8,%9}, {%0,%1,%2,%3};"
        : "+f"(c[0]), "+f"(c[1]), "+f"(c[2]), "+f"(c[3])
        : "r"(a[0]), "r"(a[1]), "r"(a[2]), "r"(a[3]), "r"(b0), "r"(b1));
}

// ---------------------------------------------------------------------------
// Alpha fp32 -> bf16; block 0 also zeroes the accumulators (fresh every replay)
// ---------------------------------------------------------------------------
__global__ void conv_alpha_kernel(const float* __restrict__ A) {
    if (blockIdx.x == 0) {
        #pragma unroll
        for (int r = 0; r < 4; ++r) g_rowsum[threadIdx.x * 4 + r] = 0.f;
        if (threadIdx.x == 0) g_loglik = 0.0;
    }
    size_t i = ((size_t)blockIdx.x * blockDim.x + threadIdx.x) * 4;
    float4 v = *reinterpret_cast<const float4*>(A + i);
    *reinterpret_cast<__nv_bfloat162*>(&g_Ab[i])     = __floats2bfloat162_rn(v.x, v.y);
    *reinterpret_cast<__nv_bfloat162*>(&g_Ab[i + 2]) = __floats2bfloat162_rn(v.z, v.w);
}

// ---------------------------------------------------------------------------
// Fused transpose + exponential scan with 64-step halo (decay <= e^-1 =>
// halo truncation error ~ e^-64, invisible) + row-sum accumulation for Mu0.
// ---------------------------------------------------------------------------
__global__ __launch_bounds__(256)
void scan_kernel(const float* __restrict__ obs, const float* __restrict__ Beta) {
    __shared__ float tile[32][321];
    const int k0 = blockIdx.y * 32;
    const int t0 = blockIdx.x * 256;
    const int tid = threadIdx.x;
    const int lane = tid & 31;
    const int tstart = t0 - 64;

    int rbase = (tid >> 5) * 4;
    float rs[4];
    #pragma unroll
    for (int r = 0; r < 4; ++r) {
        const float* src = obs + (size_t)(k0 + rbase + r) * N_DIM;
        float acc = 0.f;
        #pragma unroll
        for (int i = 0; i < 10; ++i) {
            int col = lane + i * 32;
            int t = tstart + col;
            float v = (t >= 0) ? src[t] : 0.f;
            tile[rbase + r][col] = v;
            if (i >= 2) acc += v;          // emit region only (cols 64..319)
        }
        rs[r] = acc;
    }
    #pragma unroll
    for (int r = 0; r < 4; ++r) {
        float v = rs[r];
        #pragma unroll
        for (int off = 16; off > 0; off >>= 1)
            v += __shfl_down_sync(0xFFFFFFFFu, v, off);
        if (lane == 0) atomicAdd(&g_rowsum[k0 + rbase + r], v);
    }
    __syncthreads();

    if (tid < 32) {
        float beta = Beta[k0 + tid];
        float dec = __expf(-beta);
        float S = 0.f;
        #pragma unroll 8
        for (int i = 0; i < 64; ++i) S = dec * (S + tile[tid][i]);
        #pragma unroll 4
        for (int i = 0; i < 256; ++i) {
            g_Gb[(size_t)(t0 + i) * K_DIM + k0 + tid] = __float2bfloat16(beta * S);
            S = dec * (S + tile[tid][64 + i]);
        }
    }
}

// Mu0 finalize (after all scan atomics)
__global__ void mu_kernel() {
    int k = threadIdx.x;
    g_Mu0[k] = g_rowsum[k] * (1.0f / (float)N_DIM) * 0.1f + 1e-5f;
}

// ---------------------------------------------------------------------------
// bf16 tensor-core GEMM (mma.sync m16n8k16) + fused epilogue.
// C[t][ko] = sum_j G[t][j]*Alpha[ko][j]; lam1=softplus(C); lam1[:,0]=0;
// loglik += sum(obs*log(mu+lam1+1e-5) - mu - lam1); write lam1 and lams0.
//
// CTA tile 128(t) x 256(ko), BK=32, 4-stage cp.async pipeline, 512 threads
// (16 warps, each a register-safe 64x32 tile: acc = 64 regs, no spills;
// launch_bounds(512,1) caps regs at 128). 16 warps/SM attacks the latency
// bound seen in round 4 (occ=12.5%, issue=19.9%, nothing saturated).
// SMEM rows padded to 40 bf16 (80B): stride 20 words -> conflict-free ldmatrix.
// ---------------------------------------------------------------------------
#define STAGES 4
#define A_TILE_B (128 * 80)            // 10240
#define B_TILE_B (256 * 80)            // 20480
#define STAGE_B  (A_TILE_B + B_TILE_B) // 30720
#define GEMM_SMEM (STAGES * STAGE_B)   // 122880

__global__ __launch_bounds__(512, 1)
void gemm_ep_kernel(const float* __restrict__ obs,
                    float* __restrict__ out_lams0,
                    float* __restrict__ out_lam1, int do_write) {
    extern __shared__ char smem[];
    const uint32_t sb = smem_u32(smem);
    const int tid = threadIdx.x;
    const int wid = tid >> 5;
    const int lane = tid & 31;
    const int wm = wid & 1;           // 2 m-warps of 64
    const int wn = wid >> 1;          // 8 n-warps of 32
    const int ko0 = blockIdx.x * 256;
    const int t0  = blockIdx.y * 128;

    const int lrow = tid >> 2;        // 0..127
    const int lch  = tid & 3;         // 0..3

    auto load_stage = [&](int s, int j0) {
        if (j0 < K_DIM) {
            uint32_t abase = sb + s * STAGE_B;
            uint32_t bbase = abase + A_TILE_B;
            cp16(abase + lrow * 80 + lch * 16,
                 g_Gb + (size_t)(t0 + lrow) * K_DIM + j0 + lch * 8);
            #pragma unroll
            for (int p = 0; p < 2; ++p) {
                int row = lrow + p * 128;
                cp16(bbase + row * 80 + lch * 16,
                     g_Ab + (size_t)(ko0 + row) * K_DIM + j0 + lch * 8);
            }
        }
        CP_COMMIT();
    };

    load_stage(0, 0);
    load_stage(1, 32);
    load_stage(2, 64);

    float acc[4][4][4];
    #pragma unroll
    for (int i = 0; i < 4; ++i)
        #pragma unroll
        for (int j = 0; j < 4; ++j)
            #pragma unroll
            for (int e = 0; e < 4; ++e) acc[i][j][e] = 0.f;

    const uint32_t lr = (lane & 15);
    const uint32_t lh = (lane >> 4) * 16;

    #pragma unroll 1
    for (int it = 0; it < 32; ++it) {
        CP_WAIT(2);
        __syncthreads();
        load_stage((it + 3) & 3, (it + 3) * 32);

        uint32_t abase = sb + (it & 3) * STAGE_B;
        uint32_t bbase = abase + A_TILE_B;
        #pragma unroll
        for (int kk = 0; kk < 2; ++kk) {
            uint32_t a[4][4], b[2][4];
            #pragma unroll
            for (int mi = 0; mi < 4; ++mi)
                ldsm4(a[mi], abase + (wm * 64 + mi * 16 + lr) * 80 + lh + kk * 32);
            #pragma unroll
            for (int ng = 0; ng < 2; ++ng)
                ldsm4(b[ng], bbase + (wn * 32 + ng * 16 + lr) * 80 + lh + kk * 32);
            #pragma unroll
            for (int mi = 0; mi < 4; ++mi)
                #pragma unroll
                for (int ni = 0; ni < 4; ++ni)
                    mma16816(acc[mi][ni], a[mi],
                             b[ni >> 1][ni & 1], b[ni >> 1][2 + (ni & 1)]);
        }
    }

    // ---- fused epilogue straight from mma fragments ----
    float lsum = 0.f;
    #pragma unroll
    for (int mi = 0; mi < 4; ++mi) {
        #pragma unroll
        for (int ni = 0; ni < 4; ++ni) {
            const int tb = t0 + wm * 64 + mi * 16 + (lane >> 2);
            const int kb = ko0 + wn * 32 + ni * 8 + (lane & 3) * 2;
            #pragma unroll
            for (int e = 0; e < 4; ++e) {
                const int t  = tb + (e >> 1) * 8;
                const int ko = kb + (e & 1);
                float x = acc[mi][ni][e];
                float lam1 = (x > 20.f) ? x : __logf(1.f + __expf(x));
                if (t == 0) lam1 = 0.f;
                float mu = g_Mu0[ko];
                float o = __ldg(obs + (size_t)ko * N_DIM + t);
                lsum += o * __logf(mu + lam1 + 1e-5f) - mu - lam1;
                if (do_write) {
                    out_lam1[(size_t)ko * N_DIM + t]  = lam1;
                    out_lams0[(size_t)ko * N_DIM + t] = mu;
                }
            }
        }
    }

    __syncthreads();
    float* red = reinterpret_cast<float*>(smem);
    red[tid] = lsum;
    __syncthreads();
    for (int off = 256; off > 0; off >>= 1) {
        if (tid < off) red[tid] += red[tid + off];
        __syncthreads();
    }
    if (tid == 0) atomicAdd(&g_loglik, (double)red[0]);
}

__global__ void finalize_kernel(float* __restrict__ out) {
    out[0] = (float)g_loglik;
}

// ---------------------------------------------------------------------------
extern "C" void kernel_launch(void* const* d_in, const int* in_sizes, int n_in,
                              void* d_out, int out_size) {
    const float *obs = nullptr, *Beta = nullptr, *Alpha = nullptr;
    for (int i = 0; i < n_in; ++i) {
        if (in_sizes[i] == K_DIM) Beta = (const float*)d_in[i];
        else if (in_sizes[i] == K_DIM * K_DIM) Alpha = (const float*)d_in[i];
        else if ((size_t)in_sizes[i] == (size_t)K_DIM * N_DIM) obs = (const float*)d_in[i];
    }
    float* out = (float*)d_out;
    const long long full_sz = 1LL + 2LL * K_DIM * N_DIM;
    int full = ((long long)out_size >= full_sz) ? 1 : 0;
    float* out_lams0 = out + 1;
    float* out_lam1  = out + 1 + (size_t)K_DIM * N_DIM;

    static int smem_set = 0;
    if (!smem_set) {
        cudaFuncSetAttribute(gemm_ep_kernel,
                             cudaFuncAttributeMaxDynamicSharedMemorySize, GEMM_SMEM);
        smem_set = 1;
    }

    conv_alpha_kernel<<<(K_DIM * K_DIM) / (256 * 4), 256>>>(Alpha);
    dim3 sgrid(N_DIM / 256, K_DIM / 32);
    scan_kernel<<<sgrid, 256>>>(obs, Beta);
    mu_kernel<<<1, K_DIM>>>();
    dim3 ggrid(K_DIM / 256, N_DIM / 128);
    gemm_ep_kernel<<<ggrid, 512, GEMM_SMEM>>>(obs, out_lams0, out_lam1, full);
    finalize_kernel<<<1, 1>>>(out);
}

// round 6
// speedup vs baseline: 1.3302x; 1.2778x over previous
#include <cuda_runtime.h>
#include <cuda_bf16.h>
#include <math.h>
#include <stdint.h>

#define K_DIM 1024
#define N_DIM 16384

// ---------------------------------------------------------------------------
// Scratch (static device globals — no dynamic allocation allowed)
// ---------------------------------------------------------------------------
__device__ __nv_bfloat16 g_Gb[(size_t)N_DIM * K_DIM];   // G[t][k] bf16, 32 MB
__device__ __nv_bfloat16 g_Ab[(size_t)K_DIM * K_DIM];   // Alpha bf16, 2 MB
__device__ float  g_rowsum[K_DIM];
__device__ double g_loglik;

// ---------------------------------------------------------------------------
// PTX helpers (baseline sm_80+ features only — tcgen05 not available via this
// toolchain: harness compiles for plain sm_103, arch-accelerated ops rejected)
// ---------------------------------------------------------------------------
__device__ __forceinline__ uint32_t smem_u32(const void* p) {
    uint32_t a;
    asm("{ .reg .u64 t; cvta.to.shared.u64 t, %1; cvt.u32.u64 %0, t; }"
        : "=r"(a) : "l"(p));
    return a;
}
__device__ __forceinline__ void cp16(uint32_t dst, const void* src) {
    asm volatile("cp.async.cg.shared.global [%0], [%1], 16;"
                 :: "r"(dst), "l"(src) : "memory");
}
#define CP_COMMIT() asm volatile("cp.async.commit_group;" ::: "memory")
#define CP_WAIT(n)  asm volatile("cp.async.wait_group %0;" :: "n"(n) : "memory")

__device__ __forceinline__ void ldsm4(uint32_t* r, uint32_t addr) {
    asm volatile("ldmatrix.sync.aligned.m8n8.x4.shared.b16 {%0,%1,%2,%3}, [%4];"
                 : "=r"(r[0]), "=r"(r[1]), "=r"(r[2]), "=r"(r[3]) : "r"(addr));
}
__device__ __forceinline__ void mma16816(float* c, const uint32_t* a,
                                         uint32_t b0, uint32_t b1) {
    asm volatile(
        "mma.sync.aligned.m16n8k16.row.col.f32.bf16.bf16.f32 "
        "{%0,%1,%2,%3}, {%4,%5,%6,%7}, {%8,%9}, {%0,%1,%2,%3};"
        : "+f"(c[0]), "+f"(c[1]), "+f"(c[2]), "+f"(c[3])
        : "r"(a[0]), "r"(a[1]), "r"(a[2]), "r"(a[3]), "r"(b0), "r"(b1));
}

// ---------------------------------------------------------------------------
// Alpha fp32 -> bf16; block 0 also zeroes the accumulators (fresh every replay)
// ---------------------------------------------------------------------------
__global__ void conv_alpha_kernel(const float* __restrict__ A) {
    if (blockIdx.x == 0) {
        #pragma unroll
        for (int r = 0; r < 4; ++r) g_rowsum[threadIdx.x * 4 + r] = 0.f;
        if (threadIdx.x == 0) g_loglik = 0.0;
    }
    size_t i = ((size_t)blockIdx.x * blockDim.x + threadIdx.x) * 4;
    float4 v = *reinterpret_cast<const float4*>(A + i);
    *reinterpret_cast<__nv_bfloat162*>(&g_Ab[i])     = __floats2bfloat162_rn(v.x, v.y);
    *reinterpret_cast<__nv_bfloat162*>(&g_Ab[i + 2]) = __floats2bfloat162_rn(v.z, v.w);
}

// ---------------------------------------------------------------------------
// Fused transpose + exponential scan with 64-step halo (decay <= e^-1 =>
// halo truncation error ~ e^-64, invisible) + row-sum accumulation for Mu0.
// ---------------------------------------------------------------------------
__global__ __launch_bounds__(256)
void scan_kernel(const float* __restrict__ obs, const float* __restrict__ Beta) {
    __shared__ float tile[32][321];
    const int k0 = blockIdx.y * 32;
    const int t0 = blockIdx.x * 256;
    const int tid = threadIdx.x;
    const int lane = tid & 31;
    const int tstart = t0 - 64;

    int rbase = (tid >> 5) * 4;
    float rs[4];
    #pragma unroll
    for (int r = 0; r < 4; ++r) {
        const float* src = obs + (size_t)(k0 + rbase + r) * N_DIM;
        float acc = 0.f;
        #pragma unroll
        for (int i = 0; i < 10; ++i) {
            int col = lane + i * 32;
            int t = tstart + col;
            float v = (t >= 0) ? src[t] : 0.f;
            tile[rbase + r][col] = v;
            if (i >= 2) acc += v;          // emit region only (cols 64..319)
        }
        rs[r] = acc;
    }
    #pragma unroll
    for (int r = 0; r < 4; ++r) {
        float v = rs[r];
        #pragma unroll
        for (int off = 16; off > 0; off >>= 1)
            v += __shfl_down_sync(0xFFFFFFFFu, v, off);
        if (lane == 0) atomicAdd(&g_rowsum[k0 + rbase + r], v);
    }
    __syncthreads();

    if (tid < 32) {
        float beta = Beta[k0 + tid];
        float dec = __expf(-beta);
        float S = 0.f;
        #pragma unroll 8
        for (int i = 0; i < 64; ++i) S = dec * (S + tile[tid][i]);
        #pragma unroll 4
        for (int i = 0; i < 256; ++i) {
            g_Gb[(size_t)(t0 + i) * K_DIM + k0 + tid] = __float2bfloat16(beta * S);
            S = dec * (S + tile[tid][64 + i]);
        }
    }
}

// ---------------------------------------------------------------------------
// bf16 tensor-core GEMM (mma.sync m16n8k16) + fused epilogue.
// C[t][ko] = sum_j G[t][j]*Alpha[ko][j]; lam1=softplus(C); lam1[:,0]=0;
// loglik += sum(obs*log(mu+lam1+1e-5) - mu - lam1); write lam1 and lams0.
// mu computed inline from g_rowsum (no separate kernel).
//
// CTA tile 128(t) x 128(ko), BK=32, 4-stage cp.async pipeline, 256 threads,
// __launch_bounds__(256,2): 2 CTAs/SM (smem 2x81920=160KB, regs<=128) so the
// two CTAs interleave across each other's barrier/cp.async stalls — this is
// what made round 3 faster than the single-CTA 512-thread round-5 variant.
// SMEM rows padded to 40 bf16 (80B): stride 20 words -> conflict-free ldmatrix.
// ---------------------------------------------------------------------------
#define STAGES 4
#define TILE_B 10240              // 128 rows * 80 bytes
#define STAGE_B (2 * TILE_B)      // A tile + B tile
#define GEMM_SMEM (STAGES * STAGE_B)   // 81920

__global__ __launch_bounds__(256, 2)
void gemm_ep_kernel(const float* __restrict__ obs,
                    float* __restrict__ out_lams0,
                    float* __restrict__ out_lam1, int do_write) {
    extern __shared__ char smem[];
    const uint32_t sb = smem_u32(smem);
    const int tid = threadIdx.x;
    const int wid = tid >> 5;
    const int lane = tid & 31;
    const int wm = wid & 1;           // 2 m-warps of 64
    const int wn = wid >> 1;          // 4 n-warps of 32
    const int ko0 = blockIdx.x * 128;
    const int t0  = blockIdx.y * 128;

    const int lrow = tid >> 2;        // 0..63
    const int lch  = tid & 3;         // 0..3

    auto load_stage = [&](int s, int j0) {
        if (j0 < K_DIM) {
            uint32_t abase = sb + s * STAGE_B;
            uint32_t bbase = abase + TILE_B;
            #pragma unroll
            for (int p = 0; p < 2; ++p) {
                int row = lrow + p * 64;
                uint32_t doff = row * 80 + lch * 16;
                cp16(abase + doff, g_Gb + (size_t)(t0 + row) * K_DIM + j0 + lch * 8);
                cp16(bbase + doff, g_Ab + (size_t)(ko0 + row) * K_DIM + j0 + lch * 8);
            }
        }
        CP_COMMIT();
    };

    load_stage(0, 0);
    load_stage(1, 32);
    load_stage(2, 64);

    float acc[4][4][4];
    #pragma unroll
    for (int i = 0; i < 4; ++i)
        #pragma unroll
        for (int j = 0; j < 4; ++j)
            #pragma unroll
            for (int e = 0; e < 4; ++e) acc[i][j][e] = 0.f;

    const uint32_t lr = (lane & 15);
    const uint32_t lh = (lane >> 4) * 16;

    #pragma unroll 1
    for (int it = 0; it < 32; ++it) {
        CP_WAIT(2);
        __syncthreads();
        load_stage((it + 3) & 3, (it + 3) * 32);

        uint32_t abase = sb + (it & 3) * STAGE_B;
        uint32_t bbase = abase + TILE_B;
        #pragma unroll
        for (int kk = 0; kk < 2; ++kk) {
            uint32_t a[4][4], b[2][4];
            #pragma unroll
            for (int mi = 0; mi < 4; ++mi)
                ldsm4(a[mi], abase + (wm * 64 + mi * 16 + lr) * 80 + lh + kk * 32);
            #pragma unroll
            for (int ng = 0; ng < 2; ++ng)
                ldsm4(b[ng], bbase + (wn * 32 + ng * 16 + lr) * 80 + lh + kk * 32);
            #pragma unroll
            for (int mi = 0; mi < 4; ++mi)
                #pragma unroll
                for (int ni = 0; ni < 4; ++ni)
                    mma16816(acc[mi][ni], a[mi],
                             b[ni >> 1][ni & 1], b[ni >> 1][2 + (ni & 1)]);
        }
    }

    // ---- fused epilogue straight from mma fragments ----
    const float MU_C = (1.0f / (float)N_DIM) * 0.1f;
    float lsum = 0.f;
    #pragma unroll
    for (int mi = 0; mi < 4; ++mi) {
        #pragma unroll
        for (int ni = 0; ni < 4; ++ni) {
            const int tb = t0 + wm * 64 + mi * 16 + (lane >> 2);
            const int kb = ko0 + wn * 32 + ni * 8 + (lane & 3) * 2;
            #pragma unroll
            for (int e = 0; e < 4; ++e) {
                const int t  = tb + (e >> 1) * 8;
                const int ko = kb + (e & 1);
                float x = acc[mi][ni][e];
                float lam1 = (x > 20.f) ? x : __logf(1.f + __expf(x));
                if (t == 0) lam1 = 0.f;
                float mu = __ldg(&g_rowsum[ko]) * MU_C + 1e-5f;
                float o = __ldg(obs + (size_t)ko * N_DIM + t);
                lsum += o * __logf(mu + lam1 + 1e-5f) - mu - lam1;
                if (do_write) {
                    out_lam1[(size_t)ko * N_DIM + t]  = lam1;
                    out_lams0[(size_t)ko * N_DIM + t] = mu;
                }
            }
        }
    }

    __syncthreads();
    float* red = reinterpret_cast<float*>(smem);
    red[tid] = lsum;
    __syncthreads();
    for (int off = 128; off > 0; off >>= 1) {
        if (tid < off) red[tid] += red[tid + off];
        __syncthreads();
    }
    if (tid == 0) atomicAdd(&g_loglik, (double)red[0]);
}

__global__ void finalize_kernel(float* __restrict__ out) {
    out[0] = (float)g_loglik;
}

// ---------------------------------------------------------------------------
extern "C" void kernel_launch(void* const* d_in, const int* in_sizes, int n_in,
                              void* d_out, int out_size) {
    const float *obs = nullptr, *Beta = nullptr, *Alpha = nullptr;
    for (int i = 0; i < n_in; ++i) {
        if (in_sizes[i] == K_DIM) Beta = (const float*)d_in[i];
        else if (in_sizes[i] == K_DIM * K_DIM) Alpha = (const float*)d_in[i];
        else if ((size_t)in_sizes[i] == (size_t)K_DIM * N_DIM) obs = (const float*)d_in[i];
    }
    float* out = (float*)d_out;
    const long long full_sz = 1LL + 2LL * K_DIM * N_DIM;
    int full = ((long long)out_size >= full_sz) ? 1 : 0;
    float* out_lams0 = out + 1;
    float* out_lam1  = out + 1 + (size_t)K_DIM * N_DIM;

    static int smem_set = 0;
    if (!smem_set) {
        cudaFuncSetAttribute(gemm_ep_kernel,
                             cudaFuncAttributeMaxDynamicSharedMemorySize, GEMM_SMEM);
        smem_set = 1;
    }

    conv_alpha_kernel<<<(K_DIM * K_DIM) / (256 * 4), 256>>>(Alpha);
    dim3 sgrid(N_DIM / 256, K_DIM / 32);
    scan_kernel<<<sgrid, 256>>>(obs, Beta);
    dim3 ggrid(K_DIM / 128, N_DIM / 128);
    gemm_ep_kernel<<<ggrid, 256, GEMM_SMEM>>>(obs, out_lams0, out_lam1, full);
    finalize_kernel<<<1, 1>>>(out);
}

// round 7
// speedup vs baseline: 1.4979x; 1.1260x over previous
#include <cuda_runtime.h>
#include <cuda_bf16.h>
#include <math.h>
#include <stdint.h>

#define K_DIM 1024
#define N_DIM 16384

// ---------------------------------------------------------------------------
// Scratch (static device globals — no dynamic allocation allowed)
// ---------------------------------------------------------------------------
__device__ __nv_bfloat16 g_Gb[(size_t)N_DIM * K_DIM];   // G[t][k] bf16, 32 MB
__device__ __nv_bfloat16 g_Ab[(size_t)K_DIM * K_DIM];   // Alpha bf16, 2 MB
__device__ float    g_rowsum[K_DIM];
__device__ double   g_loglik;
__device__ unsigned g_done;

// ---------------------------------------------------------------------------
// PTX helpers (baseline sm_80+ features only — tcgen05 not available via this
// toolchain: harness compiles for plain sm_103, arch-accelerated ops rejected)
// ---------------------------------------------------------------------------
__device__ __forceinline__ uint32_t smem_u32(const void* p) {
    uint32_t a;
    asm("{ .reg .u64 t; cvta.to.shared.u64 t, %1; cvt.u32.u64 %0, t; }"
        : "=r"(a) : "l"(p));
    return a;
}
__device__ __forceinline__ void cp16(uint32_t dst, const void* src) {
    asm volatile("cp.async.cg.shared.global [%0], [%1], 16;"
                 :: "r"(dst), "l"(src) : "memory");
}
#define CP_COMMIT() asm volatile("cp.async.commit_group;" ::: "memory")
#define CP_WAIT(n)  asm volatile("cp.async.wait_group %0;" :: "n"(n) : "memory")

__device__ __forceinline__ void ldsm4(uint32_t* r, uint32_t addr) {
    asm volatile("ldmatrix.sync.aligned.m8n8.x4.shared.b16 {%0,%1,%2,%3}, [%4];"
                 : "=r"(r[0]), "=r"(r[1]), "=r"(r[2]), "=r"(r[3]) : "r"(addr));
}
__device__ __forceinline__ void mma16816(float* c, const uint32_t* a,
                                         uint32_t b0, uint32_t b1) {
    asm volatile(
        "mma.sync.aligned.m16n8k16.row.col.f32.bf16.bf16.f32 "
        "{%0,%1,%2,%3}, {%4,%5,%6,%7}, {%8,%9}, {%0,%1,%2,%3};"
        : "+f"(c[0]), "+f"(c[1]), "+f"(c[2]), "+f"(c[3])
        : "r"(a[0]), "r"(a[1]), "r"(a[2]), "r"(a[3]), "r"(b0), "r"(b1));
}

// ---------------------------------------------------------------------------
// Alpha fp32 -> bf16; block 0 also zeroes the accumulators (fresh every replay)
// ---------------------------------------------------------------------------
__global__ void conv_alpha_kernel(const float* __restrict__ A) {
    if (blockIdx.x == 0) {
        #pragma unroll
        for (int r = 0; r < 4; ++r) g_rowsum[threadIdx.x * 4 + r] = 0.f;
        if (threadIdx.x == 0) { g_loglik = 0.0; g_done = 0u; }
    }
    size_t i = ((size_t)blockIdx.x * blockDim.x + threadIdx.x) * 4;
    float4 v = *reinterpret_cast<const float4*>(A + i);
    *reinterpret_cast<__nv_bfloat162*>(&g_Ab[i])     = __floats2bfloat162_rn(v.x, v.y);
    *reinterpret_cast<__nv_bfloat162*>(&g_Ab[i + 2]) = __floats2bfloat162_rn(v.z, v.w);
}

// ---------------------------------------------------------------------------
// Fused transpose + exponential scan with 64-step halo (decay <= e^-1 =>
// halo truncation error ~ e^-64, invisible) + row-sum accumulation for Mu0.
// ---------------------------------------------------------------------------
__global__ __launch_bounds__(256)
void scan_kernel(const float* __restrict__ obs, const float* __restrict__ Beta) {
    __shared__ float tile[32][321];
    const int k0 = blockIdx.y * 32;
    const int t0 = blockIdx.x * 256;
    const int tid = threadIdx.x;
    const int lane = tid & 31;
    const int tstart = t0 - 64;

    int rbase = (tid >> 5) * 4;
    float rs[4];
    #pragma unroll
    for (int r = 0; r < 4; ++r) {
        const float* src = obs + (size_t)(k0 + rbase + r) * N_DIM;
        float acc = 0.f;
        #pragma unroll
        for (int i = 0; i < 10; ++i) {
            int col = lane + i * 32;
            int t = tstart + col;
            float v = (t >= 0) ? src[t] : 0.f;
            tile[rbase + r][col] = v;
            if (i >= 2) acc += v;          // emit region only (cols 64..319)
        }
        rs[r] = acc;
    }
    #pragma unroll
    for (int r = 0; r < 4; ++r) {
        float v = rs[r];
        #pragma unroll
        for (int off = 16; off > 0; off >>= 1)
            v += __shfl_down_sync(0xFFFFFFFFu, v, off);
        if (lane == 0) atomicAdd(&g_rowsum[k0 + rbase + r], v);
    }
    __syncthreads();

    if (tid < 32) {
        float beta = Beta[k0 + tid];
        float dec = __expf(-beta);
        float S = 0.f;
        #pragma unroll 8
        for (int i = 0; i < 64; ++i) S = dec * (S + tile[tid][i]);
        #pragma unroll 4
        for (int i = 0; i < 256; ++i) {
            g_Gb[(size_t)(t0 + i) * K_DIM + k0 + tid] = __float2bfloat16(beta * S);
            S = dec * (S + tile[tid][64 + i]);
        }
    }
}

// ---------------------------------------------------------------------------
// bf16 tensor-core GEMM (mma.sync m16n8k16) + fused epilogue + fused finalize.
// C[t][ko] = sum_j G[t][j]*Alpha[ko][j]; lam1=softplus(C); lam1[:,0]=0;
// loglik += sum(obs*log(mu+lam1+1e-5) - mu - lam1); write lam1 and lams0;
// last CTA writes out[0] = loglik.
//
// CTA tile 128(t) x 128(ko), BK=64 (16 pipeline stations instead of 32),
// 3-stage cp.async pipeline, 256 threads, __launch_bounds__(256,2) ->
// 2 CTAs/SM (smem 2x96KB = 192KB, regs<=128).
// SMEM layout: 128B rows, XOR swizzle (chunk ^ row&7) -> conflict-free for
// BOTH the cp.async STS fill (round 6's 80B pad had STS conflicts) and LDSM.
// ---------------------------------------------------------------------------
#define BK 64
#define TILE_B (128 * 128)             // 16384 bytes (128 rows x 128B)
#define STAGE_B (2 * TILE_B)           // 32768: A tile + B tile
#define GSTAGES 3
#define GEMM_SMEM (GSTAGES * STAGE_B)  // 98304

__global__ __launch_bounds__(256, 2)
void gemm_ep_kernel(const float* __restrict__ obs,
                    float* __restrict__ out,
                    float* __restrict__ out_lams0,
                    float* __restrict__ out_lam1, int do_write) {
    extern __shared__ char smem[];
    const uint32_t sb = smem_u32(smem);
    const int tid = threadIdx.x;
    const int wid = tid >> 5;
    const int lane = tid & 31;
    const int wm = wid & 1;           // 2 m-warps of 64
    const int wn = wid >> 1;          // 4 n-warps of 32
    const int ko0 = blockIdx.x * 128;
    const int t0  = blockIdx.y * 128;

    // cp.async fill: 1024 16B-chunks per tile, 4 per thread; chunk c ->
    // row = c>>3, j = c&7, smem offset row*128 + ((j ^ (row&7))<<4).
    auto load_stage = [&](int s, int j0) {
        if (j0 < K_DIM) {
            uint32_t abase = sb + s * STAGE_B;
            uint32_t bbase = abase + TILE_B;
            #pragma unroll
            for (int i = 0; i < 4; ++i) {
                int c = tid + 256 * i;
                int row = c >> 3, j = c & 7;
                uint32_t doff = row * 128 + (((uint32_t)(j ^ (row & 7))) << 4);
                cp16(abase + doff, g_Gb + (size_t)(t0 + row) * K_DIM + j0 + j * 8);
                cp16(bbase + doff, g_Ab + (size_t)(ko0 + row) * K_DIM + j0 + j * 8);
            }
        }
        CP_COMMIT();
    };

    load_stage(0, 0);
    load_stage(1, BK);

    float acc[4][4][4];
    #pragma unroll
    for (int i = 0; i < 4; ++i)
        #pragma unroll
        for (int j = 0; j < 4; ++j)
            #pragma unroll
            for (int e = 0; e < 4; ++e) acc[i][j][e] = 0.f;

    const int lr = (lane & 15);
    const int lc = (lane >> 4);       // 16B-chunk half select

    int scur = 0;
    #pragma unroll 1
    for (int it = 0; it < K_DIM / BK; ++it) {
        CP_WAIT(1);
        __syncthreads();
        int sld = scur + 2; if (sld >= GSTAGES) sld -= GSTAGES;
        load_stage(sld, (it + 2) * BK);

        uint32_t abase = sb + scur * STAGE_B;
        uint32_t bbase = abase + TILE_B;
        #pragma unroll 2
        for (int kk = 0; kk < 4; ++kk) {
            const int c = kk * 2 + lc;
            uint32_t a[4][4], b[2][4];
            #pragma unroll
            for (int mi = 0; mi < 4; ++mi) {
                int row = wm * 64 + mi * 16 + lr;
                ldsm4(a[mi], abase + row * 128 + (((uint32_t)(c ^ (row & 7))) << 4));
            }
            #pragma unroll
            for (int ng = 0; ng < 2; ++ng) {
                int row = wn * 32 + ng * 16 + lr;
                ldsm4(b[ng], bbase + row * 128 + (((uint32_t)(c ^ (row & 7))) << 4));
            }
            #pragma unroll
            for (int mi = 0; mi < 4; ++mi)
                #pragma unroll
                for (int ni = 0; ni < 4; ++ni)
                    mma16816(acc[mi][ni], a[mi],
                             b[ni >> 1][ni & 1], b[ni >> 1][2 + (ni & 1)]);
        }
        if (++scur >= GSTAGES) scur -= GSTAGES;
    }

    // ---- fused epilogue straight from mma fragments ----
    const float MU_C = (1.0f / (float)N_DIM) * 0.1f;
    float lsum = 0.f;
    #pragma unroll
    for (int mi = 0; mi < 4; ++mi) {
        #pragma unroll
        for (int ni = 0; ni < 4; ++ni) {
            const int tb = t0 + wm * 64 + mi * 16 + (lane >> 2);
            const int kb = ko0 + wn * 32 + ni * 8 + (lane & 3) * 2;
            #pragma unroll
            for (int e = 0; e < 4; ++e) {
                const int t  = tb + (e >> 1) * 8;
                const int ko = kb + (e & 1);
                float x = acc[mi][ni][e];
                float lam1 = (x > 20.f) ? x : __logf(1.f + __expf(x));
                if (t == 0) lam1 = 0.f;
                float mu = __ldg(&g_rowsum[ko]) * MU_C + 1e-5f;
                float o = __ldg(obs + (size_t)ko * N_DIM + t);
                lsum += o * __logf(mu + lam1 + 1e-5f) - mu - lam1;
                if (do_write) {
                    out_lam1[(size_t)ko * N_DIM + t]  = lam1;
                    out_lams0[(size_t)ko * N_DIM + t] = mu;
                }
            }
        }
    }

    __syncthreads();
    float* red = reinterpret_cast<float*>(smem);
    red[tid] = lsum;
    __syncthreads();
    for (int off = 128; off > 0; off >>= 1) {
        if (tid < off) red[tid] += red[tid + off];
        __syncthreads();
    }
    if (tid == 0) {
        atomicAdd(&g_loglik, (double)red[0]);
        __threadfence();
        unsigned n = atomicAdd(&g_done, 1u);
        if (n == gridDim.x * gridDim.y - 1) {
            // all CTAs' loglik contributions are visible (atomic + fence chain)
            double v = atomicAdd(&g_loglik, 0.0);
            out[0] = (float)v;
        }
    }
}

// ---------------------------------------------------------------------------
extern "C" void kernel_launch(void* const* d_in, const int* in_sizes, int n_in,
                              void* d_out, int out_size) {
    const float *obs = nullptr, *Beta = nullptr, *Alpha = nullptr;
    for (int i = 0; i < n_in; ++i) {
        if (in_sizes[i] == K_DIM) Beta = (const float*)d_in[i];
        else if (in_sizes[i] == K_DIM * K_DIM) Alpha = (const float*)d_in[i];
        else if ((size_t)in_sizes[i] == (size_t)K_DIM * N_DIM) obs = (const float*)d_in[i];
    }
    float* out = (float*)d_out;
    const long long full_sz = 1LL + 2LL * K_DIM * N_DIM;
    int full = ((long long)out_size >= full_sz) ? 1 : 0;
    float* out_lams0 = out + 1;
    float* out_lam1  = out + 1 + (size_t)K_DIM * N_DIM;

    static int smem_set = 0;
    if (!smem_set) {
        cudaFuncSetAttribute(gemm_ep_kernel,
                             cudaFuncAttributeMaxDynamicSharedMemorySize, GEMM_SMEM);
        smem_set = 1;
    }

    conv_alpha_kernel<<<(K_DIM * K_DIM) / (256 * 4), 256>>>(Alpha);
    dim3 sgrid(N_DIM / 256, K_DIM / 32);
    scan_kernel<<<sgrid, 256>>>(obs, Beta);
    dim3 ggrid(K_DIM / 128, N_DIM / 128);
    gemm_ep_kernel<<<ggrid, 256, GEMM_SMEM>>>(obs, out, out_lams0, out_lam1, full);
}

// round 8
// speedup vs baseline: 1.5307x; 1.0219x over previous
#include <cuda_runtime.h>
#include <cuda_bf16.h>
#include <math.h>
#include <stdint.h>

#define K_DIM 1024
#define N_DIM 16384

// ---------------------------------------------------------------------------
// Scratch (static device globals — no dynamic allocation allowed)
// ---------------------------------------------------------------------------
__device__ __nv_bfloat16 g_Gb[(size_t)N_DIM * K_DIM];   // G[t][k] bf16, 32 MB
__device__ __nv_bfloat16 g_Ab[(size_t)K_DIM * K_DIM];   // Alpha bf16, 2 MB
__device__ float    g_rowsum[K_DIM];
__device__ double   g_loglik;
__device__ unsigned g_done;

// ---------------------------------------------------------------------------
// PTX helpers (baseline sm_80+ features only — tcgen05 not available via this
// toolchain: harness compiles for plain sm_103, arch-accelerated ops rejected)
// ---------------------------------------------------------------------------
__device__ __forceinline__ uint32_t smem_u32(const void* p) {
    uint32_t a;
    asm("{ .reg .u64 t; cvta.to.shared.u64 t, %1; cvt.u32.u64 %0, t; }"
        : "=r"(a) : "l"(p));
    return a;
}
__device__ __forceinline__ void cp16(uint32_t dst, const void* src) {
    asm volatile("cp.async.cg.shared.global [%0], [%1], 16;"
                 :: "r"(dst), "l"(src) : "memory");
}
#define CP_COMMIT() asm volatile("cp.async.commit_group;" ::: "memory")
#define CP_WAIT(n)  asm volatile("cp.async.wait_group %0;" :: "n"(n) : "memory")

__device__ __forceinline__ void ldsm4(uint32_t* r, uint32_t addr) {
    asm volatile("ldmatrix.sync.aligned.m8n8.x4.shared.b16 {%0,%1,%2,%3}, [%4];"
                 : "=r"(r[0]), "=r"(r[1]), "=r"(r[2]), "=r"(r[3]) : "r"(addr));
}
__device__ __forceinline__ void mma16816(float* c, const uint32_t* a,
                                         uint32_t b0, uint32_t b1) {
    asm volatile(
        "mma.sync.aligned.m16n8k16.row.col.f32.bf16.bf16.f32 "
        "{%0,%1,%2,%3}, {%4,%5,%6,%7}, {%8,%9}, {%0,%1,%2,%3};"
        : "+f"(c[0]), "+f"(c[1]), "+f"(c[2]), "+f"(c[3])
        : "r"(a[0]), "r"(a[1]), "r"(a[2]), "r"(a[3]), "r"(b0), "r"(b1));
}

// ---------------------------------------------------------------------------
// Alpha fp32 -> bf16; block 0 also zeroes the accumulators (fresh every replay)
// ---------------------------------------------------------------------------
__global__ void conv_alpha_kernel(const float* __restrict__ A) {
    if (blockIdx.x == 0) {
        #pragma unroll
        for (int r = 0; r < 4; ++r) g_rowsum[threadIdx.x * 4 + r] = 0.f;
        if (threadIdx.x == 0) { g_loglik = 0.0; g_done = 0u; }
    }
    size_t i = ((size_t)blockIdx.x * blockDim.x + threadIdx.x) * 4;
    float4 v = *reinterpret_cast<const float4*>(A + i);
    *reinterpret_cast<__nv_bfloat162*>(&g_Ab[i])     = __floats2bfloat162_rn(v.x, v.y);
    *reinterpret_cast<__nv_bfloat162*>(&g_Ab[i + 2]) = __floats2bfloat162_rn(v.z, v.w);
}

// ---------------------------------------------------------------------------
// Fused transpose + exponential scan + row-sum accumulation for Mu0.
// Scan phase now uses 4 warps: the 256-emit chunk is split into 4 sub-chunks
// of 64, each with its own 64-step in-smem warm-up (decay <= e^-1 => warm-up
// truncation error ~ e^-64, invisible). 128 serial steps instead of 320.
// ---------------------------------------------------------------------------
__global__ __launch_bounds__(256)
void scan_kernel(const float* __restrict__ obs, const float* __restrict__ Beta) {
    __shared__ float tile[32][321];
    const int k0 = blockIdx.y * 32;
    const int t0 = blockIdx.x * 256;
    const int tid = threadIdx.x;
    const int lane = tid & 31;
    const int tstart = t0 - 64;

    int rbase = (tid >> 5) * 4;
    float rs[4];
    #pragma unroll
    for (int r = 0; r < 4; ++r) {
        const float* src = obs + (size_t)(k0 + rbase + r) * N_DIM;
        float acc = 0.f;
        #pragma unroll
        for (int i = 0; i < 10; ++i) {
            int col = lane + i * 32;
            int t = tstart + col;
            float v = (t >= 0) ? src[t] : 0.f;
            tile[rbase + r][col] = v;
            if (i >= 2) acc += v;          // emit region only (cols 64..319)
        }
        rs[r] = acc;
    }
    #pragma unroll
    for (int r = 0; r < 4; ++r) {
        float v = rs[r];
        #pragma unroll
        for (int off = 16; off > 0; off >>= 1)
            v += __shfl_down_sync(0xFFFFFFFFu, v, off);
        if (lane == 0) atomicAdd(&g_rowsum[k0 + rbase + r], v);
    }
    __syncthreads();

    if (tid < 128) {
        const int w = tid >> 5;          // sub-chunk 0..3
        const int base = w * 64;
        float beta = Beta[k0 + lane];
        float dec = __expf(-beta);
        float S = 0.f;
        #pragma unroll 8
        for (int i = 0; i < 64; ++i) S = dec * (S + tile[lane][base + i]);
        #pragma unroll 4
        for (int i = 0; i < 64; ++i) {
            g_Gb[(size_t)(t0 + base + i) * K_DIM + k0 + lane] =
                __float2bfloat16(beta * S);
            S = dec * (S + tile[lane][base + 64 + i]);
        }
    }
}

// ---------------------------------------------------------------------------
// bf16 tensor-core GEMM (mma.sync m16n8k16) + fused epilogue + fused finalize.
// C[t][ko] = sum_j G[t][j]*Alpha[ko][j]; lam1=softplus(C); lam1[:,0]=0;
// loglik += sum(obs*log(mu+lam1+1e-5) - mu - lam1); write lam1 and lams0;
// last CTA writes out[0] = loglik.
//
// CTA tile 128(t) x 128(ko), BK=64, 3-stage cp.async pipeline, 256 threads,
// __launch_bounds__(256,2) -> 2 CTAs/SM. 128B smem rows, XOR swizzle
// (chunk ^ row&7): conflict-free STS and LDSM. NEW: explicit fragment
// double-buffering — kk+1's LDSMs issue before kk's MMAs so LDS latency
// overlaps tensor issue (2x24 frag regs + 64 acc ~ 126 regs, no spill).
// ---------------------------------------------------------------------------
#define BK 64
#define TILE_B (128 * 128)             // 16384 bytes (128 rows x 128B)
#define STAGE_B (2 * TILE_B)           // 32768: A tile + B tile
#define GSTAGES 3
#define GEMM_SMEM (GSTAGES * STAGE_B)  // 98304

__global__ __launch_bounds__(256, 2)
void gemm_ep_kernel(const float* __restrict__ obs,
                    float* __restrict__ out,
                    float* __restrict__ out_lams0,
                    float* __restrict__ out_lam1, int do_write) {
    extern __shared__ char smem[];
    const uint32_t sb = smem_u32(smem);
    const int tid = threadIdx.x;
    const int wid = tid >> 5;
    const int lane = tid & 31;
    const int wm = wid & 1;           // 2 m-warps of 64
    const int wn = wid >> 1;          // 4 n-warps of 32
    const int ko0 = blockIdx.x * 128;
    const int t0  = blockIdx.y * 128;

    // cp.async fill: 1024 16B-chunks per tile, 4 per thread; chunk c ->
    // row = c>>3, j = c&7, smem offset row*128 + ((j ^ (row&7))<<4).
    auto load_stage = [&](int s, int j0) {
        if (j0 < K_DIM) {
            uint32_t abase = sb + s * STAGE_B;
            uint32_t bbase = abase + TILE_B;
            #pragma unroll
            for (int i = 0; i < 4; ++i) {
                int c = tid + 256 * i;
                int row = c >> 3, j = c & 7;
                uint32_t doff = row * 128 + (((uint32_t)(j ^ (row & 7))) << 4);
                cp16(abase + doff, g_Gb + (size_t)(t0 + row) * K_DIM + j0 + j * 8);
                cp16(bbase + doff, g_Ab + (size_t)(ko0 + row) * K_DIM + j0 + j * 8);
            }
        }
        CP_COMMIT();
    };

    load_stage(0, 0);
    load_stage(1, BK);

    float acc[4][4][4];
    #pragma unroll
    for (int i = 0; i < 4; ++i)
        #pragma unroll
        for (int j = 0; j < 4; ++j)
            #pragma unroll
            for (int e = 0; e < 4; ++e) acc[i][j][e] = 0.f;

    const int lr  = (lane & 15);
    const int lc  = (lane >> 4);       // 16B-chunk half select
    const int lr7 = lr & 7;            // row&7 is lane-invariant across mi/ng

    // per-lane row byte offsets (stage-relative)
    uint32_t arow[4], brow[2];
    #pragma unroll
    for (int mi = 0; mi < 4; ++mi) arow[mi] = (wm * 64 + mi * 16 + lr) * 128;
    #pragma unroll
    for (int ng = 0; ng < 2; ++ng) brow[ng] = (wn * 32 + ng * 16 + lr) * 128;

    int scur = 0;
    #pragma unroll 1
    for (int it = 0; it < K_DIM / BK; ++it) {
        CP_WAIT(1);
        __syncthreads();
        int sld = scur + 2; if (sld >= GSTAGES) sld -= GSTAGES;
        load_stage(sld, (it + 2) * BK);

        uint32_t abase = sb + scur * STAGE_B;
        uint32_t bbase = abase + TILE_B;

        uint32_t afr[2][4][4], bfr[2][2][4];
        // preload fragments for kk = 0
        {
            uint32_t xo = ((uint32_t)((0 * 2 + lc) ^ lr7)) << 4;
            #pragma unroll
            for (int mi = 0; mi < 4; ++mi) ldsm4(afr[0][mi], abase + arow[mi] + xo);
            #pragma unroll
            for (int ng = 0; ng < 2; ++ng) ldsm4(bfr[0][ng], bbase + brow[ng] + xo);
        }
        #pragma unroll
        for (int kk = 0; kk < 4; ++kk) {
            const int cb = kk & 1, nb = cb ^ 1;
            if (kk < 3) {
                uint32_t xo = ((uint32_t)(((kk + 1) * 2 + lc) ^ lr7)) << 4;
                #pragma unroll
                for (int mi = 0; mi < 4; ++mi)
                    ldsm4(afr[nb][mi], abase + arow[mi] + xo);
                #pragma unroll
                for (int ng = 0; ng < 2; ++ng)
                    ldsm4(bfr[nb][ng], bbase + brow[ng] + xo);
            }
            #pragma unroll
            for (int mi = 0; mi < 4; ++mi)
                #pragma unroll
                for (int ni = 0; ni < 4; ++ni)
                    mma16816(acc[mi][ni], afr[cb][mi],
                             bfr[cb][ni >> 1][ni & 1], bfr[cb][ni >> 1][2 + (ni & 1)]);
        }
        if (++scur >= GSTAGES) scur -= GSTAGES;
    }

    // ---- fused epilogue straight from mma fragments ----
    const float MU_C = (1.0f / (float)N_DIM) * 0.1f;
    float lsum = 0.f;
    #pragma unroll
    for (int mi = 0; mi < 4; ++mi) {
        #pragma unroll
        for (int ni = 0; ni < 4; ++ni) {
            const int tb = t0 + wm * 64 + mi * 16 + (lane >> 2);
            const int kb = ko0 + wn * 32 + ni * 8 + (lane & 3) * 2;
            #pragma unroll
            for (int e = 0; e < 4; ++e) {
                const int t  = tb + (e >> 1) * 8;
                const int ko = kb + (e & 1);
                float x = acc[mi][ni][e];
                float lam1 = (x > 20.f) ? x : __logf(1.f + __expf(x));
                if (t == 0) lam1 = 0.f;
                float mu = __ldg(&g_rowsum[ko]) * MU_C + 1e-5f;
                float o = __ldg(obs + (size_t)ko * N_DIM + t);
                lsum += o * __logf(mu + lam1 + 1e-5f) - mu - lam1;
                if (do_write) {
                    out_lam1[(size_t)ko * N_DIM + t]  = lam1;
                    out_lams0[(size_t)ko * N_DIM + t] = mu;
                }
            }
        }
    }

    __syncthreads();
    float* red = reinterpret_cast<float*>(smem);
    red[tid] = lsum;
    __syncthreads();
    for (int off = 128; off > 0; off >>= 1) {
        if (tid < off) red[tid] += red[tid + off];
        __syncthreads();
    }
    if (tid == 0) {
        atomicAdd(&g_loglik, (double)red[0]);
        __threadfence();
        unsigned n = atomicAdd(&g_done, 1u);
        if (n == gridDim.x * gridDim.y - 1) {
            double v = atomicAdd(&g_loglik, 0.0);
            out[0] = (float)v;
        }
    }
}

// ---------------------------------------------------------------------------
extern "C" void kernel_launch(void* const* d_in, const int* in_sizes, int n_in,
                              void* d_out, int out_size) {
    const float *obs = nullptr, *Beta = nullptr, *Alpha = nullptr;
    for (int i = 0; i < n_in; ++i) {
        if (in_sizes[i] == K_DIM) Beta = (const float*)d_in[i];
        else if (in_sizes[i] == K_DIM * K_DIM) Alpha = (const float*)d_in[i];
        else if ((size_t)in_sizes[i] == (size_t)K_DIM * N_DIM) obs = (const float*)d_in[i];
    }
    float* out = (float*)d_out;
    const long long full_sz = 1LL + 2LL * K_DIM * N_DIM;
    int full = ((long long)out_size >= full_sz) ? 1 : 0;
    float* out_lams0 = out + 1;
    float* out_lam1  = out + 1 + (size_t)K_DIM * N_DIM;

    static int smem_set = 0;
    if (!smem_set) {
        cudaFuncSetAttribute(gemm_ep_kernel,
                             cudaFuncAttributeMaxDynamicSharedMemorySize, GEMM_SMEM);
        smem_set = 1;
    }

    conv_alpha_kernel<<<(K_DIM * K_DIM) / (256 * 4), 256>>>(Alpha);
    dim3 sgrid(N_DIM / 256, K_DIM / 32);
    scan_kernel<<<sgrid, 256>>>(obs, Beta);
    dim3 ggrid(K_DIM / 128, N_DIM / 128);
    gemm_ep_kernel<<<ggrid, 256, GEMM_SMEM>>>(obs, out, out_lams0, out_lam1, full);
}